// round 8
// baseline (speedup 1.0000x reference)
#include <cuda_runtime.h>
#include <cuda_fp16.h>

#define NN 100000
#define NE 1000000
#define CH 128
#define BN_EPS 1e-5f

#define BN_BLKS 592
#define NSLOT (BN_BLKS * 8)                      // 4736
#define HIST_BLKS ((NE + 255) / 256)             // 3907
#define NCHUNK ((NN + 511) / 512)                // 196
#define FOLD_BLKS 128
#define GEMM_TM 64
#define GEMM_BLKS ((NN + GEMM_TM - 1) / GEMM_TM) // 1563
#define GATH_BLKS ((NN * 32 + 255) / 256)        // 12500

// ---------------- scratch ----------------
__device__ __align__(16) __half g_bufA[NN * CH];   // h (fp16)
__device__ __align__(16) __half g_bufB[NN * CH];   // y1 (fp16)
__device__ __align__(16) float g_dinv[NN];
__device__ int   g_cnt[NN];        // zero-init; re-zeroed by k_rezero each replay
__device__ int   g_fillc[NN];
__device__ int   g_off[NN + 1];
__device__ __align__(16) int2 g_edge[NE];          // (src, fp32-bits of dinv[s]*dinv[d])
__device__ __align__(16) float g_part[BN_BLKS * 256];
__device__ __align__(16) float g_Wt[CH * CH];
__device__ __align__(16) float g_bb[CH];
__device__ volatile unsigned long long g_lb[NCHUNK];

// ================= BN partial body (fp32 input) =================
__device__ __forceinline__ void bn_body_f32(const float* __restrict__ X, int b, int tid) {
    __shared__ float4 shs[256];
    __shared__ float4 shss[256];
    int lane = tid & 31;
    int r = tid >> 5;
    float4 s = make_float4(0.f, 0.f, 0.f, 0.f);
    float4 ss = make_float4(0.f, 0.f, 0.f, 0.f);
    const float4* X4 = (const float4*)X;
    for (int row = b * 8 + r; row < NN; row += NSLOT) {
        float4 v = X4[(size_t)row * 32 + lane];
        s.x += v.x; s.y += v.y; s.z += v.z; s.w += v.w;
        ss.x += v.x*v.x; ss.y += v.y*v.y; ss.z += v.z*v.z; ss.w += v.w*v.w;
    }
    shs[tid] = s; shss[tid] = ss;
    __syncthreads();
    if (r == 0) {
#pragma unroll
        for (int w = 1; w < 8; w++) {
            float4 a = shs[w * 32 + lane];
            float4 bq = shss[w * 32 + lane];
            s.x += a.x; s.y += a.y; s.z += a.z; s.w += a.w;
            ss.x += bq.x; ss.y += bq.y; ss.z += bq.z; ss.w += bq.w;
        }
        float4* P4 = (float4*)g_part;
        P4[b * 64 + lane] = s;
        P4[b * 64 + 32 + lane] = ss;
    }
}

// ================= BN partial body (fp16 input) =================
__device__ __forceinline__ void bn_body_f16(const __half* __restrict__ X, int b, int tid) {
    __shared__ float4 shs[256];
    __shared__ float4 shss[256];
    int lane = tid & 31;
    int r = tid >> 5;
    float4 s = make_float4(0.f, 0.f, 0.f, 0.f);
    float4 ss = make_float4(0.f, 0.f, 0.f, 0.f);
    const uint2* X2 = (const uint2*)X;
    for (int row = b * 8 + r; row < NN; row += NSLOT) {
        uint2 raw = X2[(size_t)row * 32 + lane];
        __half2 h0 = *reinterpret_cast<__half2*>(&raw.x);
        __half2 h1 = *reinterpret_cast<__half2*>(&raw.y);
        float2 f0 = __half22float2(h0);
        float2 f1 = __half22float2(h1);
        s.x += f0.x; s.y += f0.y; s.z += f1.x; s.w += f1.y;
        ss.x += f0.x*f0.x; ss.y += f0.y*f0.y; ss.z += f1.x*f1.x; ss.w += f1.y*f1.y;
    }
    shs[tid] = s; shss[tid] = ss;
    __syncthreads();
    if (r == 0) {
#pragma unroll
        for (int w = 1; w < 8; w++) {
            float4 a = shs[w * 32 + lane];
            float4 bq = shss[w * 32 + lane];
            s.x += a.x; s.y += a.y; s.z += a.z; s.w += a.w;
            ss.x += bq.x; ss.y += bq.y; ss.z += bq.z; ss.w += bq.w;
        }
        float4* P4 = (float4*)g_part;
        P4[b * 64 + lane] = s;
        P4[b * 64 + 32 + lane] = ss;
    }
}

// ================= fold body =================
__device__ __forceinline__ void fold_body(const float* __restrict__ W,
                                          const float* __restrict__ gamma,
                                          const float* __restrict__ beta,
                                          int j, int tid) {
    __shared__ float red[128];
    if (tid < 128) {
        int c = tid;
        float s = 0.f, ss = 0.f;
#pragma unroll 4
        for (int i = 0; i < BN_BLKS; i++) {
            s += g_part[i * 256 + c];
            ss += g_part[i * 256 + 128 + c];
        }
        float inv_n = 1.0f / (float)NN;
        float mean = s * inv_n;
        float var = ss * inv_n - mean * mean;
        if (var < 0.f) var = 0.f;
        float sc = gamma[c] * rsqrtf(var + BN_EPS);
        float sh = beta[c] - mean * sc;
        float w = W[j * CH + c];
        g_Wt[c * CH + j] = w * sc;
        red[c] = w * sh;
    }
    __syncthreads();
    for (int off = 64; off > 0; off >>= 1) {
        if (tid < off) red[tid] += red[tid + off];
        __syncthreads();
    }
    if (tid == 0) g_bb[j] = red[0];
}

// ================= scan body (packed-word decoupled lookback) =================
__device__ __forceinline__ void scan_body(int b, int t) {
    __shared__ int sh[256];
    __shared__ int sbase;
    int g0 = b * 512 + t * 2;
    int c0 = (g0 < NN) ? g_cnt[g0] : 0;
    int c1 = (g0 + 1 < NN) ? g_cnt[g0 + 1] : 0;
    if (g0 < NN)     g_dinv[g0]     = rsqrtf((float)c0 + 1.0f);
    if (g0 + 1 < NN) g_dinv[g0 + 1] = rsqrtf((float)c1 + 1.0f);
    int tv = c0 + c1;
    sh[t] = tv;
    __syncthreads();
    for (int off = 1; off < 256; off <<= 1) {
        int a = (t >= off) ? sh[t - off] : 0;
        __syncthreads();
        sh[t] += a;
        __syncthreads();
    }
    int incl = sh[t];
    int total = sh[255];
    if (t == 0) {
        int run = 0;
        if (b == 0) {
            g_lb[0] = (2ULL << 62) | (unsigned)total;
            g_off[0] = 0;
        } else {
            g_lb[b] = (1ULL << 62) | (unsigned)total;
            int p = b - 1;
            while (true) {
                unsigned long long w;
                do { w = g_lb[p]; } while ((w >> 62) == 0ULL);
                run += (int)(w & 0xffffffffULL);
                if ((w >> 62) == 2ULL) break;
                p--;
            }
            g_lb[b] = (2ULL << 62) | (unsigned)(run + total);
        }
        sbase = run;
    }
    __syncthreads();
    int base = sbase + incl - tv;
    if (g0 < NN)     g_off[g0 + 1] = base + c0;
    if (g0 + 1 < NN) g_off[g0 + 2] = base + c0 + c1;
}

// ================= GEMM body: C(fp16) = A @ Wt + bb =================
template <bool IS_F16_IN>
__device__ __forceinline__ void gemm_body(const void* __restrict__ Av, __half* __restrict__ C,
                                          int blk, int tid) {
    extern __shared__ float smem[];
    float* sW = smem;                 // [128][128]
    float* sX = smem + CH * CH;       // [64][128]
    const int tx = tid & 31;
    const int ty = tid >> 5;
    const int row0 = blk * GEMM_TM;

    const float4* Wt4 = (const float4*)g_Wt;
    float4* sW4 = (float4*)sW;
#pragma unroll
    for (int i = 0; i < 16; i++) sW4[tid + i * 256] = Wt4[tid + i * 256];

    float4* sX4 = (float4*)sX;
#pragma unroll
    for (int i = 0; i < 8; i++) {
        int idx = tid + i * 256;
        int rr = idx >> 5, cc = idx & 31;
        int gr = row0 + rr;
        float4 v = make_float4(0.f, 0.f, 0.f, 0.f);
        if (gr < NN) {
            if (IS_F16_IN) {
                uint2 raw = ((const uint2*)Av)[(size_t)gr * 32 + cc];
                __half2 h0 = *reinterpret_cast<__half2*>(&raw.x);
                __half2 h1 = *reinterpret_cast<__half2*>(&raw.y);
                float2 f0 = __half22float2(h0);
                float2 f1 = __half22float2(h1);
                v = make_float4(f0.x, f0.y, f1.x, f1.y);
            } else {
                v = ((const float4*)Av)[(size_t)gr * 32 + cc];
            }
        }
        sX4[idx] = v;
    }
    __syncthreads();

    float acc[8][4];
#pragma unroll
    for (int i = 0; i < 8; i++) { acc[i][0]=0.f; acc[i][1]=0.f; acc[i][2]=0.f; acc[i][3]=0.f; }

    const float* xrow = &sX[(ty * 8) * CH];
#pragma unroll 8
    for (int k = 0; k < CH; k++) {
        float4 wv = *(const float4*)(&sW[k * CH + (tx << 2)]);
#pragma unroll
        for (int i = 0; i < 8; i++) {
            float xv = xrow[i * CH + k];
            acc[i][0] = fmaf(xv, wv.x, acc[i][0]);
            acc[i][1] = fmaf(xv, wv.y, acc[i][1]);
            acc[i][2] = fmaf(xv, wv.z, acc[i][2]);
            acc[i][3] = fmaf(xv, wv.w, acc[i][3]);
        }
    }

    float4 bb = *(const float4*)&g_bb[tx << 2];
    uint2* C2 = (uint2*)C;
#pragma unroll
    for (int i = 0; i < 8; i++) {
        int r = row0 + ty * 8 + i;
        if (r < NN) {
            __half2 p0 = __floats2half2_rn(acc[i][0] + bb.x, acc[i][1] + bb.y);
            __half2 p1 = __floats2half2_rn(acc[i][2] + bb.z, acc[i][3] + bb.w);
            uint2 pk;
            pk.x = *reinterpret_cast<unsigned*>(&p0);
            pk.y = *reinterpret_cast<unsigned*>(&p1);
            C2[(size_t)r * 32 + tx] = pk;
        }
    }
}

// ================= gather core (H fp16, packed edges, fp32 accumulate) =================
__device__ __forceinline__ float4 gather_core(const __half* __restrict__ H, int node, int lane) {
    float dd = g_dinv[node];
    const uint2* H2 = (const uint2*)H;

    uint2 hr = H2[(size_t)node * 32 + lane];
    __half2 a0 = *reinterpret_cast<__half2*>(&hr.x);
    __half2 a1 = *reinterpret_cast<__half2*>(&hr.y);
    float2 f0 = __half22float2(a0);
    float2 f1 = __half22float2(a1);
    float sc = dd * dd;
    float4 acc = make_float4(f0.x * sc, f0.y * sc, f1.x * sc, f1.y * sc);

    int beg = g_off[node];
    int end = g_off[node + 1];
    for (int base = beg; base < end; base += 32) {
        int cnt = min(32, end - base);
        int sidx = 0; float wgt = 0.f;
        if (lane < cnt) {
            int2 e = g_edge[base + lane];      // ONE coalesced 8B/lane load
            sidx = e.x;
            wgt = __int_as_float(e.y);         // dinv[s]*dinv[d], fully folded
        }
        int t = 0;
        for (; t + 8 <= cnt; t += 8) {
            int ss[8]; float ww[8]; uint2 v[8];
#pragma unroll
            for (int u = 0; u < 8; u++) {
                ss[u] = __shfl_sync(0xffffffffu, sidx, t + u);
                ww[u] = __shfl_sync(0xffffffffu, wgt, t + u);
            }
#pragma unroll
            for (int u = 0; u < 8; u++) v[u] = H2[(size_t)ss[u] * 32 + lane];
#pragma unroll
            for (int u = 0; u < 8; u++) {
                __half2 h0 = *reinterpret_cast<__half2*>(&v[u].x);
                __half2 h1 = *reinterpret_cast<__half2*>(&v[u].y);
                float2 g0 = __half22float2(h0);
                float2 g1 = __half22float2(h1);
                acc.x = fmaf(g0.x, ww[u], acc.x);
                acc.y = fmaf(g0.y, ww[u], acc.y);
                acc.z = fmaf(g1.x, ww[u], acc.z);
                acc.w = fmaf(g1.y, ww[u], acc.w);
            }
        }
        if (t < cnt) {
            int rem = cnt - t;
            int ss[8]; float ww[8]; uint2 v[8];
#pragma unroll
            for (int u = 0; u < 8; u++) {
                int tt = (u < rem) ? t + u : t;
                ss[u] = __shfl_sync(0xffffffffu, sidx, tt);
                ww[u] = __shfl_sync(0xffffffffu, wgt, tt);
            }
#pragma unroll
            for (int u = 0; u < 8; u++) {
                v[u] = (u < rem) ? H2[(size_t)ss[u] * 32 + lane] : make_uint2(0u, 0u);
            }
#pragma unroll
            for (int u = 0; u < 8; u++) {
                float wu = (u < rem) ? ww[u] : 0.f;
                __half2 h0 = *reinterpret_cast<__half2*>(&v[u].x);
                __half2 h1 = *reinterpret_cast<__half2*>(&v[u].y);
                float2 g0 = __half22float2(h0);
                float2 g1 = __half22float2(h1);
                acc.x = fmaf(g0.x, wu, acc.x);
                acc.y = fmaf(g0.y, wu, acc.y);
                acc.z = fmaf(g1.x, wu, acc.z);
                acc.w = fmaf(g1.y, wu, acc.w);
            }
        }
    }
    return acc;
}

// layer-1 gather: OUT fp16 = relu(agg + bias)
__global__ void k_gather1(const __half* __restrict__ H, __half* __restrict__ OUT,
                          const float* __restrict__ bias) {
    int node = (blockIdx.x * blockDim.x + threadIdx.x) >> 5;
    int lane = threadIdx.x & 31;
    if (node >= NN) return;
    float4 acc = gather_core(H, node, lane);
    float4 bv = ((const float4*)bias)[lane];
    acc.x = fmaxf(acc.x + bv.x, 0.f); acc.y = fmaxf(acc.y + bv.y, 0.f);
    acc.z = fmaxf(acc.z + bv.z, 0.f); acc.w = fmaxf(acc.w + bv.w, 0.f);
    __half2 p0 = __floats2half2_rn(acc.x, acc.y);
    __half2 p1 = __floats2half2_rn(acc.z, acc.w);
    uint2 pk;
    pk.x = *reinterpret_cast<unsigned*>(&p0);
    pk.y = *reinterpret_cast<unsigned*>(&p1);
    ((uint2*)OUT)[(size_t)node * 32 + lane] = pk;
}

// layer-2 gather: OUT fp32 = relu(agg + bias) + x (fp32)
__global__ void k_gather2(const __half* __restrict__ H, float* __restrict__ OUT,
                          const float* __restrict__ bias, const float* __restrict__ xres) {
    int node = (blockIdx.x * blockDim.x + threadIdx.x) >> 5;
    int lane = threadIdx.x & 31;
    if (node >= NN) return;
    float4 acc = gather_core(H, node, lane);
    float4 bv = ((const float4*)bias)[lane];
    float4 xv = ((const float4*)xres)[(size_t)node * 32 + lane];
    acc.x = fmaxf(acc.x + bv.x, 0.f) + xv.x;
    acc.y = fmaxf(acc.y + bv.y, 0.f) + xv.y;
    acc.z = fmaxf(acc.z + bv.z, 0.f) + xv.z;
    acc.w = fmaxf(acc.w + bv.w, 0.f) + xv.w;
    ((float4*)OUT)[(size_t)node * 32 + lane] = acc;
}

// ================= fused kernels =================
__global__ void k_bnhist(const float* __restrict__ X, const int* __restrict__ dst) {
    if (blockIdx.x < BN_BLKS) {
        bn_body_f32(X, blockIdx.x, threadIdx.x);
    } else {
        int e = (blockIdx.x - BN_BLKS) * 256 + threadIdx.x;
        if (e < NE) atomicAdd(&g_cnt[dst[e]], 1);
    }
}

__global__ void k_foldscan(const float* __restrict__ W,
                           const float* __restrict__ gamma, const float* __restrict__ beta) {
    if (blockIdx.x < FOLD_BLKS) {
        fold_body(W, gamma, beta, blockIdx.x, threadIdx.x);
    } else {
        scan_body(blockIdx.x - FOLD_BLKS, threadIdx.x);
    }
}

__global__ void __launch_bounds__(256) k_gemmfill(const float* __restrict__ A, __half* __restrict__ C,
                                                  const int* __restrict__ src, const int* __restrict__ dst) {
    if (blockIdx.x < GEMM_BLKS) {
        gemm_body<false>(A, C, blockIdx.x, threadIdx.x);
    } else {
        int e = (blockIdx.x - GEMM_BLKS) * 256 + threadIdx.x;
        if (e < NE) {
            int d = dst[e];
            int s = src[e];
            int pos = g_off[d] + atomicAdd(&g_fillc[d], 1);
            float w = g_dinv[s] * g_dinv[d];
            g_edge[pos] = make_int2(s, __float_as_int(w));
        }
    }
}

__global__ void k_bn16(const __half* __restrict__ X) {
    bn_body_f16(X, blockIdx.x, threadIdx.x);
}

__global__ void k_fold(const float* __restrict__ W,
                       const float* __restrict__ gamma, const float* __restrict__ beta) {
    fold_body(W, gamma, beta, blockIdx.x, threadIdx.x);
}

__global__ void __launch_bounds__(256) k_gemm16(const __half* __restrict__ A, __half* __restrict__ C) {
    gemm_body<true>(A, C, blockIdx.x, threadIdx.x);
}

// tail kernel: restore zeroed state for the next graph replay
__global__ void k_rezero() {
    int i = blockIdx.x * blockDim.x + threadIdx.x;
    if (i < NN) { g_cnt[i] = 0; g_fillc[i] = 0; }
    if (i < NCHUNK) g_lb[i] = 0ULL;
}

// ================= launch =================
extern "C" void kernel_launch(void* const* d_in, const int* in_sizes, int n_in,
                              void* d_out, int out_size) {
    const float* x      = (const float*)d_in[0];
    const int*   ei     = (const int*)d_in[1];
    const float* W1     = (const float*)d_in[2];
    const float* b1     = (const float*)d_in[3];
    const float* W2     = (const float*)d_in[4];
    const float* b2     = (const float*)d_in[5];
    const float* gamma1 = (const float*)d_in[6];
    const float* beta1  = (const float*)d_in[7];
    const float* gamma2 = (const float*)d_in[8];
    const float* beta2  = (const float*)d_in[9];
    float* out = (float*)d_out;
    const int* src = ei;
    const int* dst = ei + NE;

    cudaFuncSetAttribute(k_gemmfill, cudaFuncAttributeMaxDynamicSharedMemorySize, 98304);
    cudaFuncSetAttribute(k_gemm16,   cudaFuncAttributeMaxDynamicSharedMemorySize, 98304);

    // ---- layer 1 ----
    k_bnhist<<<BN_BLKS + HIST_BLKS, 256>>>(x, dst);                          // 1
    k_foldscan<<<FOLD_BLKS + NCHUNK, 256>>>(W1, gamma1, beta1);              // 2
    k_gemmfill<<<GEMM_BLKS + HIST_BLKS, 256, 98304>>>(x, g_bufA, src, dst);  // 3
    k_gather1<<<GATH_BLKS, 256>>>(g_bufA, g_bufB, b1);                       // 4 <-- profiled

    // ---- layer 2 ----
    k_bn16<<<BN_BLKS, 256>>>(g_bufB);                                        // 5
    k_fold<<<FOLD_BLKS, 128>>>(W2, gamma2, beta2);                           // 6
    k_gemm16<<<GEMM_BLKS, 256, 98304>>>(g_bufB, g_bufA);                     // 7
    k_gather2<<<GATH_BLKS, 256>>>(g_bufA, out, b2, x);                       // 8

    // restore zeroed state for next replay
    k_rezero<<<(NN + 255) / 256, 256>>>();                                   // 9
}

// round 9
// speedup vs baseline: 1.0031x; 1.0031x over previous
#include <cuda_runtime.h>
#include <cuda_fp16.h>

#define NN 100000
#define NE 1000000
#define CH 128
#define BN_EPS 1e-5f

#define BN_BLKS 592
#define NSLOT (BN_BLKS * 8)                      // 4736
#define HIST_BLKS ((NE + 255) / 256)             // 3907
#define NCHUNK ((NN + 511) / 512)                // 196
#define FOLD_BLKS 128
#define GEMM_TM 64
#define GEMM_BLKS ((NN + GEMM_TM - 1) / GEMM_TM) // 1563
#define GATH_BLKS ((NN * 64 + 255) / 256)        // 25000  (2 warps per node)

// ---------------- scratch ----------------
__device__ __align__(16) __half g_bufA[NN * CH];   // h (fp16)
__device__ __align__(16) __half g_bufB[NN * CH];   // y1 (fp16)
__device__ __align__(16) float g_dinv[NN];
__device__ int   g_cnt[NN];        // zero-init; re-zeroed by k_rezero each replay
__device__ int   g_fillc[NN];
__device__ int   g_off[NN + 1];
__device__ __align__(16) int2 g_edge[NE];          // (src, fp32-bits of dinv[s]*dinv[d])
__device__ __align__(16) float g_part[BN_BLKS * 256];
__device__ __align__(16) float g_Wt[CH * CH];
__device__ __align__(16) float g_bb[CH];
__device__ volatile unsigned long long g_lb[NCHUNK];

// ================= BN partial body (fp32 input) =================
__device__ __forceinline__ void bn_body_f32(const float* __restrict__ X, int b, int tid) {
    __shared__ float4 shs[256];
    __shared__ float4 shss[256];
    int lane = tid & 31;
    int r = tid >> 5;
    float4 s = make_float4(0.f, 0.f, 0.f, 0.f);
    float4 ss = make_float4(0.f, 0.f, 0.f, 0.f);
    const float4* X4 = (const float4*)X;
    for (int row = b * 8 + r; row < NN; row += NSLOT) {
        float4 v = X4[(size_t)row * 32 + lane];
        s.x += v.x; s.y += v.y; s.z += v.z; s.w += v.w;
        ss.x += v.x*v.x; ss.y += v.y*v.y; ss.z += v.z*v.z; ss.w += v.w*v.w;
    }
    shs[tid] = s; shss[tid] = ss;
    __syncthreads();
    if (r == 0) {
#pragma unroll
        for (int w = 1; w < 8; w++) {
            float4 a = shs[w * 32 + lane];
            float4 bq = shss[w * 32 + lane];
            s.x += a.x; s.y += a.y; s.z += a.z; s.w += a.w;
            ss.x += bq.x; ss.y += bq.y; ss.z += bq.z; ss.w += bq.w;
        }
        float4* P4 = (float4*)g_part;
        P4[b * 64 + lane] = s;
        P4[b * 64 + 32 + lane] = ss;
    }
}

// ================= BN partial body (fp16 input) =================
__device__ __forceinline__ void bn_body_f16(const __half* __restrict__ X, int b, int tid) {
    __shared__ float4 shs[256];
    __shared__ float4 shss[256];
    int lane = tid & 31;
    int r = tid >> 5;
    float4 s = make_float4(0.f, 0.f, 0.f, 0.f);
    float4 ss = make_float4(0.f, 0.f, 0.f, 0.f);
    const uint2* X2 = (const uint2*)X;
    for (int row = b * 8 + r; row < NN; row += NSLOT) {
        uint2 raw = X2[(size_t)row * 32 + lane];
        __half2 h0 = *reinterpret_cast<__half2*>(&raw.x);
        __half2 h1 = *reinterpret_cast<__half2*>(&raw.y);
        float2 f0 = __half22float2(h0);
        float2 f1 = __half22float2(h1);
        s.x += f0.x; s.y += f0.y; s.z += f1.x; s.w += f1.y;
        ss.x += f0.x*f0.x; ss.y += f0.y*f0.y; ss.z += f1.x*f1.x; ss.w += f1.y*f1.y;
    }
    shs[tid] = s; shss[tid] = ss;
    __syncthreads();
    if (r == 0) {
#pragma unroll
        for (int w = 1; w < 8; w++) {
            float4 a = shs[w * 32 + lane];
            float4 bq = shss[w * 32 + lane];
            s.x += a.x; s.y += a.y; s.z += a.z; s.w += a.w;
            ss.x += bq.x; ss.y += bq.y; ss.z += bq.z; ss.w += bq.w;
        }
        float4* P4 = (float4*)g_part;
        P4[b * 64 + lane] = s;
        P4[b * 64 + 32 + lane] = ss;
    }
}

// ================= fold body =================
__device__ __forceinline__ void fold_body(const float* __restrict__ W,
                                          const float* __restrict__ gamma,
                                          const float* __restrict__ beta,
                                          int j, int tid) {
    __shared__ float red[128];
    if (tid < 128) {
        int c = tid;
        float s = 0.f, ss = 0.f;
#pragma unroll 4
        for (int i = 0; i < BN_BLKS; i++) {
            s += g_part[i * 256 + c];
            ss += g_part[i * 256 + 128 + c];
        }
        float inv_n = 1.0f / (float)NN;
        float mean = s * inv_n;
        float var = ss * inv_n - mean * mean;
        if (var < 0.f) var = 0.f;
        float sc = gamma[c] * rsqrtf(var + BN_EPS);
        float sh = beta[c] - mean * sc;
        float w = W[j * CH + c];
        g_Wt[c * CH + j] = w * sc;
        red[c] = w * sh;
    }
    __syncthreads();
    for (int off = 64; off > 0; off >>= 1) {
        if (tid < off) red[tid] += red[tid + off];
        __syncthreads();
    }
    if (tid == 0) g_bb[j] = red[0];
}

// ================= scan body (packed-word decoupled lookback) =================
__device__ __forceinline__ void scan_body(int b, int t) {
    __shared__ int sh[256];
    __shared__ int sbase;
    int g0 = b * 512 + t * 2;
    int c0 = (g0 < NN) ? g_cnt[g0] : 0;
    int c1 = (g0 + 1 < NN) ? g_cnt[g0 + 1] : 0;
    if (g0 < NN)     g_dinv[g0]     = rsqrtf((float)c0 + 1.0f);
    if (g0 + 1 < NN) g_dinv[g0 + 1] = rsqrtf((float)c1 + 1.0f);
    int tv = c0 + c1;
    sh[t] = tv;
    __syncthreads();
    for (int off = 1; off < 256; off <<= 1) {
        int a = (t >= off) ? sh[t - off] : 0;
        __syncthreads();
        sh[t] += a;
        __syncthreads();
    }
    int incl = sh[t];
    int total = sh[255];
    if (t == 0) {
        int run = 0;
        if (b == 0) {
            g_lb[0] = (2ULL << 62) | (unsigned)total;
            g_off[0] = 0;
        } else {
            g_lb[b] = (1ULL << 62) | (unsigned)total;
            int p = b - 1;
            while (true) {
                unsigned long long w;
                do { w = g_lb[p]; } while ((w >> 62) == 0ULL);
                run += (int)(w & 0xffffffffULL);
                if ((w >> 62) == 2ULL) break;
                p--;
            }
            g_lb[b] = (2ULL << 62) | (unsigned)(run + total);
        }
        sbase = run;
    }
    __syncthreads();
    int base = sbase + incl - tv;
    if (g0 < NN)     g_off[g0 + 1] = base + c0;
    if (g0 + 1 < NN) g_off[g0 + 2] = base + c0 + c1;
}

// ================= GEMM body: C(fp16) = A @ Wt + bb =================
template <bool IS_F16_IN>
__device__ __forceinline__ void gemm_body(const void* __restrict__ Av, __half* __restrict__ C,
                                          int blk, int tid) {
    extern __shared__ float smem[];
    float* sW = smem;                 // [128][128]
    float* sX = smem + CH * CH;       // [64][128]
    const int tx = tid & 31;
    const int ty = tid >> 5;
    const int row0 = blk * GEMM_TM;

    const float4* Wt4 = (const float4*)g_Wt;
    float4* sW4 = (float4*)sW;
#pragma unroll
    for (int i = 0; i < 16; i++) sW4[tid + i * 256] = Wt4[tid + i * 256];

    float4* sX4 = (float4*)sX;
#pragma unroll
    for (int i = 0; i < 8; i++) {
        int idx = tid + i * 256;
        int rr = idx >> 5, cc = idx & 31;
        int gr = row0 + rr;
        float4 v = make_float4(0.f, 0.f, 0.f, 0.f);
        if (gr < NN) {
            if (IS_F16_IN) {
                uint2 raw = ((const uint2*)Av)[(size_t)gr * 32 + cc];
                __half2 h0 = *reinterpret_cast<__half2*>(&raw.x);
                __half2 h1 = *reinterpret_cast<__half2*>(&raw.y);
                float2 f0 = __half22float2(h0);
                float2 f1 = __half22float2(h1);
                v = make_float4(f0.x, f0.y, f1.x, f1.y);
            } else {
                v = ((const float4*)Av)[(size_t)gr * 32 + cc];
            }
        }
        sX4[idx] = v;
    }
    __syncthreads();

    float acc[8][4];
#pragma unroll
    for (int i = 0; i < 8; i++) { acc[i][0]=0.f; acc[i][1]=0.f; acc[i][2]=0.f; acc[i][3]=0.f; }

    const float* xrow = &sX[(ty * 8) * CH];
#pragma unroll 8
    for (int k = 0; k < CH; k++) {
        float4 wv = *(const float4*)(&sW[k * CH + (tx << 2)]);
#pragma unroll
        for (int i = 0; i < 8; i++) {
            float xv = xrow[i * CH + k];
            acc[i][0] = fmaf(xv, wv.x, acc[i][0]);
            acc[i][1] = fmaf(xv, wv.y, acc[i][1]);
            acc[i][2] = fmaf(xv, wv.z, acc[i][2]);
            acc[i][3] = fmaf(xv, wv.w, acc[i][3]);
        }
    }

    float4 bb = *(const float4*)&g_bb[tx << 2];
    uint2* C2 = (uint2*)C;
#pragma unroll
    for (int i = 0; i < 8; i++) {
        int r = row0 + ty * 8 + i;
        if (r < NN) {
            __half2 p0 = __floats2half2_rn(acc[i][0] + bb.x, acc[i][1] + bb.y);
            __half2 p1 = __floats2half2_rn(acc[i][2] + bb.z, acc[i][3] + bb.w);
            uint2 pk;
            pk.x = *reinterpret_cast<unsigned*>(&p0);
            pk.y = *reinterpret_cast<unsigned*>(&p1);
            C2[(size_t)r * 32 + tx] = pk;
        }
    }
}

// ================= gather core: 2 warps per node, half2 per lane =================
// Returns fp32 accumulated pair for channels (2*col, 2*col+1), col = half*32+lane.
__device__ __forceinline__ float2 gather_core2(const __half* __restrict__ H, int node, int col, int lane) {
    float dd = g_dinv[node];
    const unsigned* H1 = (const unsigned*)H;   // one half2 (4B) per unit; row = 64 units

    unsigned hv = H1[(size_t)node * 64 + col];
    __half2 hh = *reinterpret_cast<__half2*>(&hv);
    float2 hf = __half22float2(hh);
    float sc = dd * dd;
    float2 acc = make_float2(hf.x * sc, hf.y * sc);

    int beg = g_off[node];
    int end = g_off[node + 1];
    for (int base = beg; base < end; base += 32) {
        int cnt = min(32, end - base);
        int sidx = 0; float wgt = 0.f;
        if (lane < cnt) {
            int2 e = g_edge[base + lane];
            sidx = e.x;
            wgt = __int_as_float(e.y);
        }
        int t = 0;
        for (; t + 8 <= cnt; t += 8) {
            int ss[8]; float ww[8]; unsigned v[8];
#pragma unroll
            for (int u = 0; u < 8; u++) {
                ss[u] = __shfl_sync(0xffffffffu, sidx, t + u);
                ww[u] = __shfl_sync(0xffffffffu, wgt, t + u);
            }
#pragma unroll
            for (int u = 0; u < 8; u++) v[u] = H1[(size_t)ss[u] * 64 + col];
#pragma unroll
            for (int u = 0; u < 8; u++) {
                __half2 h2 = *reinterpret_cast<__half2*>(&v[u]);
                float2 g = __half22float2(h2);
                acc.x = fmaf(g.x, ww[u], acc.x);
                acc.y = fmaf(g.y, ww[u], acc.y);
            }
        }
        if (t < cnt) {
            int rem = cnt - t;
            int ss[8]; float ww[8]; unsigned v[8];
#pragma unroll
            for (int u = 0; u < 8; u++) {
                int tt = (u < rem) ? t + u : t;
                ss[u] = __shfl_sync(0xffffffffu, sidx, tt);
                ww[u] = __shfl_sync(0xffffffffu, wgt, tt);
            }
#pragma unroll
            for (int u = 0; u < 8; u++)
                v[u] = (u < rem) ? H1[(size_t)ss[u] * 64 + col] : 0u;
#pragma unroll
            for (int u = 0; u < 8; u++) {
                float wu = (u < rem) ? ww[u] : 0.f;
                __half2 h2 = *reinterpret_cast<__half2*>(&v[u]);
                float2 g = __half22float2(h2);
                acc.x = fmaf(g.x, wu, acc.x);
                acc.y = fmaf(g.y, wu, acc.y);
            }
        }
    }
    return acc;
}

// layer-1 gather: OUT fp16 = relu(agg + bias); 2 warps per node
__global__ void __launch_bounds__(256, 8) k_gather1(const __half* __restrict__ H, __half* __restrict__ OUT,
                                                    const float* __restrict__ bias) {
    int gw = (blockIdx.x * blockDim.x + threadIdx.x) >> 5;
    int node = gw >> 1;
    int lane = threadIdx.x & 31;
    int col = ((gw & 1) << 5) + lane;   // 0..63 half2 units
    if (node >= NN) return;
    float2 acc = gather_core2(H, node, col, lane);
    float2 bv = ((const float2*)bias)[col];
    acc.x = fmaxf(acc.x + bv.x, 0.f);
    acc.y = fmaxf(acc.y + bv.y, 0.f);
    __half2 p = __floats2half2_rn(acc.x, acc.y);
    ((unsigned*)OUT)[(size_t)node * 64 + col] = *reinterpret_cast<unsigned*>(&p);
}

// layer-2 gather: OUT fp32 = relu(agg + bias) + x; 2 warps per node
__global__ void __launch_bounds__(256, 8) k_gather2(const __half* __restrict__ H, float* __restrict__ OUT,
                                                    const float* __restrict__ bias, const float* __restrict__ xres) {
    int gw = (blockIdx.x * blockDim.x + threadIdx.x) >> 5;
    int node = gw >> 1;
    int lane = threadIdx.x & 31;
    int col = ((gw & 1) << 5) + lane;
    if (node >= NN) return;
    float2 acc = gather_core2(H, node, col, lane);
    float2 bv = ((const float2*)bias)[col];
    float2 xv = ((const float2*)xres)[(size_t)node * 64 + col];
    acc.x = fmaxf(acc.x + bv.x, 0.f) + xv.x;
    acc.y = fmaxf(acc.y + bv.y, 0.f) + xv.y;
    ((float2*)OUT)[(size_t)node * 64 + col] = acc;
}

// ================= fused kernels =================
__global__ void k_bnhist(const float* __restrict__ X, const int* __restrict__ dst) {
    if (blockIdx.x < BN_BLKS) {
        bn_body_f32(X, blockIdx.x, threadIdx.x);
    } else {
        int e = (blockIdx.x - BN_BLKS) * 256 + threadIdx.x;
        if (e < NE) atomicAdd(&g_cnt[dst[e]], 1);
    }
}

__global__ void k_foldscan(const float* __restrict__ W,
                           const float* __restrict__ gamma, const float* __restrict__ beta) {
    if (blockIdx.x < FOLD_BLKS) {
        fold_body(W, gamma, beta, blockIdx.x, threadIdx.x);
    } else {
        scan_body(blockIdx.x - FOLD_BLKS, threadIdx.x);
    }
}

__global__ void __launch_bounds__(256) k_gemmfill(const float* __restrict__ A, __half* __restrict__ C,
                                                  const int* __restrict__ src, const int* __restrict__ dst) {
    if (blockIdx.x < GEMM_BLKS) {
        gemm_body<false>(A, C, blockIdx.x, threadIdx.x);
    } else {
        int e = (blockIdx.x - GEMM_BLKS) * 256 + threadIdx.x;
        if (e < NE) {
            int d = dst[e];
            int s = src[e];
            int pos = g_off[d] + atomicAdd(&g_fillc[d], 1);
            float w = g_dinv[s] * g_dinv[d];
            g_edge[pos] = make_int2(s, __float_as_int(w));
        }
    }
}

__global__ void k_bn16(const __half* __restrict__ X) {
    bn_body_f16(X, blockIdx.x, threadIdx.x);
}

__global__ void k_fold(const float* __restrict__ W,
                       const float* __restrict__ gamma, const float* __restrict__ beta) {
    fold_body(W, gamma, beta, blockIdx.x, threadIdx.x);
}

__global__ void __launch_bounds__(256) k_gemm16(const __half* __restrict__ A, __half* __restrict__ C) {
    gemm_body<true>(A, C, blockIdx.x, threadIdx.x);
}

// tail kernel: restore zeroed state for the next graph replay
__global__ void k_rezero() {
    int i = blockIdx.x * blockDim.x + threadIdx.x;
    if (i < NN) { g_cnt[i] = 0; g_fillc[i] = 0; }
    if (i < NCHUNK) g_lb[i] = 0ULL;
}

// ================= launch =================
extern "C" void kernel_launch(void* const* d_in, const int* in_sizes, int n_in,
                              void* d_out, int out_size) {
    const float* x      = (const float*)d_in[0];
    const int*   ei     = (const int*)d_in[1];
    const float* W1     = (const float*)d_in[2];
    const float* b1     = (const float*)d_in[3];
    const float* W2     = (const float*)d_in[4];
    const float* b2     = (const float*)d_in[5];
    const float* gamma1 = (const float*)d_in[6];
    const float* beta1  = (const float*)d_in[7];
    const float* gamma2 = (const float*)d_in[8];
    const float* beta2  = (const float*)d_in[9];
    float* out = (float*)d_out;
    const int* src = ei;
    const int* dst = ei + NE;

    cudaFuncSetAttribute(k_gemmfill, cudaFuncAttributeMaxDynamicSharedMemorySize, 98304);
    cudaFuncSetAttribute(k_gemm16,   cudaFuncAttributeMaxDynamicSharedMemorySize, 98304);

    // ---- layer 1 ----
    k_bnhist<<<BN_BLKS + HIST_BLKS, 256>>>(x, dst);                          // 1
    k_foldscan<<<FOLD_BLKS + NCHUNK, 256>>>(W1, gamma1, beta1);              // 2
    k_gemmfill<<<GEMM_BLKS + HIST_BLKS, 256, 98304>>>(x, g_bufA, src, dst);  // 3
    k_gather1<<<GATH_BLKS, 256>>>(g_bufA, g_bufB, b1);                       // 4 <-- profiled

    // ---- layer 2 ----
    k_bn16<<<BN_BLKS, 256>>>(g_bufB);                                        // 5
    k_fold<<<FOLD_BLKS, 128>>>(W2, gamma2, beta2);                           // 6
    k_gemm16<<<GEMM_BLKS, 256, 98304>>>(g_bufB, g_bufA);                     // 7
    k_gather2<<<GATH_BLKS, 256>>>(g_bufA, out, b2, x);                       // 8

    // restore zeroed state for next replay
    k_rezero<<<(NN + 255) / 256, 256>>>();                                   // 9
}